// round 9
// baseline (speedup 1.0000x reference)
#include <cuda_runtime.h>
#include <math.h>
#include <stdint.h>

#define NB   262144
#define H1C  128
#define H2C  256
#define H3C  200
#define GC   25
#define DC   4
#define GDC  100

// -------------------------------------------------- pair-interleaved weights
// [kpair][2n + h] = W[n][2*kp + h]
__device__ float g_W2P[64 * 512];     // W2: k=128 -> 64 kp, n=256
__device__ float g_W3P[128 * 448];    // W3: k=256 -> 128 kp, n padded 200->224
__device__ float g_WpP[100 * 256];    // Wp: k=200 -> 100 kp, n padded 100->128

// ------------------------------------------------------------ f32x2 helpers
__device__ __forceinline__ float2 upk2(uint64_t v) {
    float2 r;
    asm("mov.b64 {%0, %1}, %2;" : "=f"(r.x), "=f"(r.y) : "l"(v));
    return r;
}
__device__ __forceinline__ void fma2(uint64_t& d, uint64_t a, uint64_t b) {
    asm("fma.rn.f32x2 %0, %1, %2, %0;" : "+l"(d) : "l"(a), "l"(b));
}

// ------------------------------------------------------------------- prep
__global__ void k_prep(const float* __restrict__ W2, const float* __restrict__ W3,
                       const float* __restrict__ Wp) {
    int stride = gridDim.x * blockDim.x;
    int i0 = blockIdx.x * blockDim.x + threadIdx.x;
    for (int i = i0; i < 64 * 512; i += stride) {
        int kp = i >> 9, rem = i & 511, n = rem >> 1, h = rem & 1;
        g_W2P[i] = W2[n * H1C + 2 * kp + h];
    }
    for (int i = i0; i < 128 * 448; i += stride) {
        int kp = i / 448, rem = i % 448, n = rem >> 1, h = rem & 1;
        g_W3P[i] = (n < 200) ? W3[n * H2C + 2 * kp + h] : 0.f;
    }
    for (int i = i0; i < 100 * 256; i += stride) {
        int kp = i >> 8, rem = i & 255, n = rem >> 1, h = rem & 1;
        g_WpP[i] = (n < 100) ? Wp[n * H3C + 2 * kp + h] : 0.f;
    }
}

// ------------------------------------------------------------- fused kernel
// 64 rows per CTA, 512 threads (16 warps x 4 rows). k-split u64 accumulators:
// acc.x sums even-k, acc.y odd-k; A = LDS.64 of consecutive k (no pk2);
// B = pair-interleaved LDS.64.  smem (floats):
//   ACT  @ [0, 16384)        h1s[64][128] -> h2s[64][256] -> h3s[64][200]
//   WBUF @ [16384, 49152)    W2P full(32768) / W3P panel(14336) / WpP(25600)
//   lps  @ [41984, 48384)    [64][100]
__global__ __launch_bounds__(512, 1) void k_fused(
        const float* __restrict__ x0,   const float* __restrict__ W1,
        const float* __restrict__ b1,   const float* __restrict__ b2,
        const float* __restrict__ b3,
        const float* __restrict__ gumbel, const float* __restrict__ rnd,
        const float* __restrict__ Wmu,  const float* __restrict__ bmu,
        const float* __restrict__ Wsig, const float* __restrict__ bsig,
        const float* __restrict__ bpai, float* __restrict__ out) {
    extern __shared__ float sm[];
    float* h1s = sm;              // [64][128]
    float* h2s = sm;              // [64][256] overlay
    float* h3s = sm;              // [64][200] overlay
    float* WB  = sm + 16384;      // weight buffer
    float* lps = sm + 41984;      // [64][100]
    __shared__ float xs[64 * 3], W1s[H1C * 3], b1s[H1C], b2s[H2C], b3s[H3C], bps[GDC];
    __shared__ int idxs[256];

    const int tid  = threadIdx.x;
    const int wid  = tid >> 5, lane = tid & 31;
    const int b0   = blockIdx.x * 64;
    const int r0   = wid * 4;            // 4 rows per warp

    // ---- stage constants + full W2 pair image (128KB)
    for (int e = tid; e < H1C * 3; e += 512) W1s[e] = W1[e];
    if (tid < H1C) b1s[tid] = b1[tid];
    if (tid < H2C) b2s[tid] = b2[tid];
    if (tid < H3C) b3s[tid] = b3[tid];
    if (tid < GDC) bps[tid] = bpai[tid];
    for (int e = tid; e < 64 * 3; e += 512) xs[e] = x0[(size_t)b0 * 3 + e];
    {
        float4* dst = (float4*)WB;
        const float4* src = (const float4*)g_W2P;
        for (int e = tid; e < 8192; e += 512) dst[e] = src[e];
    }
    __syncthreads();

    // ---- layer 1: h1 = relu(x0 @ W1^T + b1)
    for (int e = tid; e < 64 * H1C; e += 512) {
        int r = e >> 7, j = e & 127;
        float v = fmaf(xs[r * 3 + 0], W1s[j * 3 + 0],
                  fmaf(xs[r * 3 + 1], W1s[j * 3 + 1],
                  fmaf(xs[r * 3 + 2], W1s[j * 3 + 2], b1s[j])));
        h1s[e] = fmaxf(v, 0.f);
    }
    __syncthreads();

    // ---- layer 2: [64 x 256], 64 k-pairs, full-width warp tile 4r x 256n
    uint64_t a2acc[4][8];
#pragma unroll
    for (int r = 0; r < 4; r++)
#pragma unroll
        for (int j = 0; j < 8; j++) a2acc[r][j] = 0ull;

#pragma unroll 2
    for (int kp = 0; kp < 64; kp++) {
        const uint64_t* bp = (const uint64_t*)(WB + kp * 512);
        uint64_t bv[8];
#pragma unroll
        for (int j = 0; j < 8; j++) bv[j] = bp[lane + 32 * j];
#pragma unroll
        for (int r = 0; r < 4; r++) {
            uint64_t a2 = *(const uint64_t*)(h1s + (r0 + r) * H1C + 2 * kp);
#pragma unroll
            for (int j = 0; j < 8; j++) fma2(a2acc[r][j], a2, bv[j]);
        }
    }
    __syncthreads();   // all reads of h1s/WB done before overwrite

    // epilogue: h2 = relu(acc.x + acc.y + b2); col n = lane + 32j
#pragma unroll
    for (int r = 0; r < 4; r++)
#pragma unroll
        for (int j = 0; j < 8; j++) {
            int n = lane + 32 * j;
            float2 v = upk2(a2acc[r][j]);
            h2s[(r0 + r) * H2C + n] = fmaxf(v.x + v.y + b2s[n], 0.f);
        }
    __syncthreads();

    // ---- layer 3: [64 x 200(224)], 128 k-pairs in 2 panels of 64
    uint64_t a3acc[4][7];
#pragma unroll
    for (int r = 0; r < 4; r++)
#pragma unroll
        for (int j = 0; j < 7; j++) a3acc[r][j] = 0ull;

    for (int pan = 0; pan < 2; pan++) {
        {
            float4* dst = (float4*)WB;
            const float4* src = (const float4*)(g_W3P + pan * 28672);
            for (int e = tid; e < 7168; e += 512) dst[e] = src[e];
        }
        __syncthreads();
#pragma unroll 2
        for (int kp = 0; kp < 64; kp++) {
            const uint64_t* bp = (const uint64_t*)(WB + kp * 448);
            uint64_t bv[7];
#pragma unroll
            for (int j = 0; j < 7; j++) bv[j] = bp[lane + 32 * j];
#pragma unroll
            for (int r = 0; r < 4; r++) {
                uint64_t a2 = *(const uint64_t*)(h2s + (r0 + r) * H2C
                                                 + pan * 128 + 2 * kp);
#pragma unroll
                for (int j = 0; j < 7; j++) fma2(a3acc[r][j], a2, bv[j]);
            }
        }
        __syncthreads();   // panel reads done before reload / h3 overlay
    }

    // epilogue: h3 = relu(acc.x + acc.y + b3); cols n = lane + 32j < 200
#pragma unroll
    for (int r = 0; r < 4; r++) {
#pragma unroll
        for (int j = 0; j < 6; j++) {
            int n = lane + 32 * j;
            float2 v = upk2(a3acc[r][j]);
            h3s[(r0 + r) * H3C + n] = fmaxf(v.x + v.y + b3s[n], 0.f);
        }
        if (lane < 8) {
            int n = lane + 192;
            float2 v = upk2(a3acc[r][6]);
            h3s[(r0 + r) * H3C + n] = fmaxf(v.x + v.y + b3s[n], 0.f);
        }
    }
    __syncthreads();

    // ---- pi GEMM: [64 x 100(128)], 100 k-pairs, single full weight image
    {
        float4* dst = (float4*)WB;
        const float4* src = (const float4*)g_WpP;
        for (int e = tid; e < 6400; e += 512) dst[e] = src[e];
    }
    __syncthreads();

    uint64_t apacc[4][4];
#pragma unroll
    for (int r = 0; r < 4; r++)
#pragma unroll
        for (int j = 0; j < 4; j++) apacc[r][j] = 0ull;

#pragma unroll 2
    for (int kp = 0; kp < 100; kp++) {
        const uint64_t* bp = (const uint64_t*)(WB + kp * 256);
        uint64_t bv[4];
#pragma unroll
        for (int j = 0; j < 4; j++) bv[j] = bp[lane + 32 * j];
#pragma unroll
        for (int r = 0; r < 4; r++) {
            uint64_t a2 = *(const uint64_t*)(h3s + (r0 + r) * H3C + 2 * kp);
#pragma unroll
            for (int j = 0; j < 4; j++) fma2(apacc[r][j], a2, bv[j]);
        }
    }

    // lps = log(|pi + b| + eps); cols n = lane + 32j < 100
#pragma unroll
    for (int r = 0; r < 4; r++) {
#pragma unroll
        for (int j = 0; j < 3; j++) {
            int n = lane + 32 * j;
            float2 v = upk2(apacc[r][j]);
            lps[(r0 + r) * GDC + n] = logf(fabsf(v.x + v.y + bps[n]) + 1e-12f);
        }
        if (lane < 4) {
            int n = lane + 96;
            float2 v = upk2(apacc[r][3]);
            lps[(r0 + r) * GDC + n] = logf(fabsf(v.x + v.y + bps[n]) + 1e-12f);
        }
    }
    __syncthreads();

    // ---- Gumbel-argmax per (row, d): threads 0..255
    if (tid < 256) {
        int r = tid >> 2, d = tid & 3;
        const float* gp = gumbel + (size_t)(b0 + r) * GDC + d;
        float best = -1e30f;
        int bg = 0;
#pragma unroll
        for (int g = 0; g < GC; g++) {
            float v = lps[r * GDC + g * 4 + d] + gp[g * 4];
            if (v > best) { best = v; bg = g; }
        }
        idxs[tid] = bg;
    }
    __syncthreads();

    // ---- selection: 8 lanes per pair, 4 pairs per warp per iter, 4 iters
    const int sl = lane & 7, grp = lane >> 3;
    for (int it = 0; it < 4; it++) {
        int pp = wid * 16 + it * 4 + grp;        // pair index in [0,256)
        int r = pp >> 2, d = pp & 3;
        int head = idxs[pp] * 4 + d;
        const float4* wm = (const float4*)(Wmu  + (size_t)head * H3C);
        const float4* ws = (const float4*)(Wsig + (size_t)head * H3C);
        const float4* hv = (const float4*)(h3s + r * H3C);

        float smu = 0.f, ssg = 0.f;
#pragma unroll
        for (int j = 0; j < 6; j++) {
            int i4 = sl + 8 * j;
            float4 h = hv[i4];
            float4 m = wm[i4];
            float4 s = ws[i4];
            smu = fmaf(h.x, m.x, fmaf(h.y, m.y, fmaf(h.z, m.z, fmaf(h.w, m.w, smu))));
            ssg = fmaf(h.x, s.x, fmaf(h.y, s.y, fmaf(h.z, s.z, fmaf(h.w, s.w, ssg))));
        }
        if (sl < 2) {
            int i4 = 48 + sl;
            float4 h = hv[i4];
            float4 m = wm[i4];
            float4 s = ws[i4];
            smu = fmaf(h.x, m.x, fmaf(h.y, m.y, fmaf(h.z, m.z, fmaf(h.w, m.w, smu))));
            ssg = fmaf(h.x, s.x, fmaf(h.y, s.y, fmaf(h.z, s.z, fmaf(h.w, s.w, ssg))));
        }
#pragma unroll
        for (int off = 4; off > 0; off >>= 1) {
            smu += __shfl_xor_sync(0xffffffffu, smu, off);
            ssg += __shfl_xor_sync(0xffffffffu, ssg, off);
        }
        if (sl == 0) {
            float mu = smu + bmu[head];
            float sg = fabsf(ssg + bsig[head]);
            size_t oi = (size_t)(b0 + r) * DC + d;
            out[oi] = rnd[oi] * sg + mu;
        }
    }
}

// ---------------------------------------------------------------- launch
extern "C" void kernel_launch(void* const* d_in, const int* in_sizes, int n_in,
                              void* d_out, int out_size) {
    const float* x0   = (const float*)d_in[0];
    const float* rnd  = (const float*)d_in[1];
    const float* gum  = (const float*)d_in[2];
    const float* W1   = (const float*)d_in[3];
    const float* b1   = (const float*)d_in[4];
    const float* W2   = (const float*)d_in[5];
    const float* b2   = (const float*)d_in[6];
    const float* W3   = (const float*)d_in[7];
    const float* b3   = (const float*)d_in[8];
    const float* Wmu  = (const float*)d_in[9];
    const float* bmu  = (const float*)d_in[10];
    const float* Wsig = (const float*)d_in[11];
    const float* bsig = (const float*)d_in[12];
    const float* Wpai = (const float*)d_in[13];
    const float* bpai = (const float*)d_in[14];
    float* out = (float*)d_out;

    const size_t smF = 49152 * sizeof(float);   // 196608 B

    cudaFuncSetAttribute(k_fused, cudaFuncAttributeMaxDynamicSharedMemorySize, (int)smF);

    k_prep <<<64, 256>>>(W2, W3, Wpai);
    k_fused<<<NB / 64, 512, smF>>>(x0, W1, b1, b2, b3,
                                   gum, rnd, Wmu, bmu, Wsig, bsig, bpai, out);
}